// round 16
// baseline (speedup 1.0000x reference)
#include <cuda_runtime.h>
#include <cuda_fp16.h>
#include <cstdint>

#define N_NODES 100000
#define N_EDGES 1600000
#define IN_CH   128
#define HIDDEN  64
#define NCLS    40

// ---------------- scratch (device globals; no allocation allowed) ----------
__device__ int   g_is64;
__device__ int   g_deg[N_NODES];       // zero at load; re-zeroed by agg2 tail
__device__ int   g_off[N_NODES + 1];
__device__ float g_dinv[N_NODES];
__device__ int   g_bsum[128];          // lookback partials (sentinel +1); reset by deg
__device__ unsigned g_rank[N_EDGES];   // (dst<<15) | rank-within-dst (from deg atomic)
__device__ int   g_adj[N_EDGES];       // plain src index, dst-grouped
__device__ __align__(16) __half g_hw  [(size_t)N_NODES * HIDDEN];  // dinv*(X@W1) fp16
__device__ __align__(16) __half g_agg1[(size_t)N_NODES * HIDDEN];  // layer1 agg (fp16)
__device__ __align__(16) __half g_h2w [(size_t)N_NODES * NCLS];    // dinv*(relu@W2) fp16

// ---------------- helpers ----------------------------------------------------
__device__ __forceinline__ void h8_to_f8(uint4 v, float* f) {
    float2 t;
    t = __half22float2(*(__half2*)&v.x); f[0] = t.x; f[1] = t.y;
    t = __half22float2(*(__half2*)&v.y); f[2] = t.x; f[3] = t.y;
    t = __half22float2(*(__half2*)&v.z); f[4] = t.x; f[5] = t.y;
    t = __half22float2(*(__half2*)&v.w); f[6] = t.x; f[7] = t.y;
}
__device__ __forceinline__ unsigned pack_h2(float a, float b) {
    __half2 h = __float22half2_rn(make_float2(a, b));
    return *(unsigned*)&h;
}
__device__ __forceinline__ unsigned relu_h2(unsigned v) {
    __half2 h = *(__half2*)&v;
    h = __hmax2(h, __half2half2(__ushort_as_half(0)));
    return *(unsigned*)&h;
}

#define NB_EDGE4 1563
#define EDGE4_T  (NB_EDGE4 * 256)
#define SCAN_NB  128
#define SCAN_TPB 256
#define SCAN_PER 4        // 128*256*4 = 131072 >= N_NODES

// ---------------- deg: dtype detect + degree histogram + (dst,rank) capture -
__global__ void deg_kernel(const int* __restrict__ w) {
    int v = w[2 * threadIdx.x + 1] | w[2 * ((int)threadIdx.x + 256) + 1];
    int is64 = !__syncthreads_or(v);
    if (blockIdx.x == 0) {
        if (threadIdx.x == 0) g_is64 = is64;
        if (threadIdx.x < SCAN_NB) g_bsum[threadIdx.x] = 0;
    }

    int idx = blockIdx.x * 256 + threadIdx.x;
#pragma unroll
    for (int j = 0; j < 4; j++) {
        int e = idx + j * EDGE4_T;
        if (e < N_EDGES) {
            int d = is64 ? w[2 * (N_EDGES + e)] : w[N_EDGES + e];
            if ((unsigned)d >= N_NODES) d = 0;
            unsigned r = (unsigned)atomicAdd(&g_deg[d], 1);
            // pack dst (17b) + rank (15b); masked rank stays in-bounds always
            g_rank[e] = ((unsigned)d << 15) | (r & 0x7FFFu);
        }
    }
}

// ---------------- single-kernel exclusive scan (decoupled lookback) ---------
__global__ void scan_kernel() {
    __shared__ int p[SCAN_TPB];
    __shared__ int red[SCAN_TPB];
    const int t = threadIdx.x;
    const int bid = blockIdx.x;

    int base = (bid * SCAN_TPB + t) * SCAN_PER;
    int loc[SCAN_PER];
    int s = 0;
#pragma unroll
    for (int j = 0; j < SCAN_PER; j++) {
        int i = base + j;
        int d = (i < N_NODES) ? g_deg[i] : 0;
        loc[j] = s;
        s += d;
    }
    p[t] = s;
    __syncthreads();
    for (int o = 1; o < SCAN_TPB; o <<= 1) {
        int v = (t >= o) ? p[t - o] : 0;
        __syncthreads();
        p[t] += v;
        __syncthreads();
    }
    int total = p[SCAN_TPB - 1];

    if (t == 0) {
        __threadfence();
        atomicExch(&g_bsum[bid], total + 1);   // publish with sentinel
    }

    int v = 0;
    if (t < bid) {
        while ((v = atomicAdd(&g_bsum[t], 0)) == 0) { }
        v -= 1;
    }
    red[t] = v;
    __syncthreads();
    for (int o = SCAN_TPB / 2; o > 0; o >>= 1) {
        if (t < o) red[t] += red[t + o];
        __syncthreads();
    }
    int bpre = red[0];
    if (bid == SCAN_NB - 1 && t == 0) g_off[N_NODES] = bpre + total;

    int pre = bpre + ((t > 0) ? p[t - 1] : 0);
#pragma unroll
    for (int j = 0; j < SCAN_PER; j++) {
        int i = base + j;
        if (i < N_NODES) {
            g_off[i] = pre + loc[j];
            g_dinv[i] = rsqrtf((float)(g_deg[i] + 1));  // +1 self loop
        }
    }
}

// counting-sort edges by dst; dst+rank from packed word (no edge dst re-read)
__global__ void fill_kernel(const int* __restrict__ w) {
    int idx = blockIdx.x * 256 + threadIdx.x;
    int is64 = g_is64;
#pragma unroll
    for (int j = 0; j < 4; j++) {
        int e = idx + j * EDGE4_T;
        if (e < N_EDGES) {
            int s = is64 ? w[2 * e] : w[e];
            if ((unsigned)s >= N_NODES) s = 0;
            unsigned pr = g_rank[e];
            int d = (int)(pr >> 15);
            g_adj[g_off[d] + (int)(pr & 0x7FFFu)] = s;
        }
    }
}

// ---------------- GEMM1 (tensor core, A direct from gmem, pipelined) --------
// fp16 C[M,64] = dinv[m] * (A[M,128](fp32) @ W[128,64]); 8 warps x 16 rows.
#define SW_PITCH 72

__global__ __launch_bounds__(256) void gemm1_kernel(const float* __restrict__ A,
                                                    const float* __restrict__ W,
                                                    __half* __restrict__ C, int M) {
    __shared__ __half sW[128 * SW_PITCH];
    const int tid = threadIdx.x;

    for (int i = tid; i < 128 * 16; i += 256) {
        int r  = i >> 4;
        int c4 = (i & 15) * 4;
        float4 a = *(const float4*)(W + r * HIDDEN + c4);
        *(uint2*)(sW + r * SW_PITCH + c4) = make_uint2(pack_h2(a.x, a.y), pack_h2(a.z, a.w));
    }
    __syncthreads();

    const int warp = tid >> 5, lane = tid & 31;
    const int r0 = blockIdx.x * 128 + warp * 16 + (lane >> 2);
    const int r1 = r0 + 8;
    const float* pA0 = A + (size_t)(r0 < M ? r0 : 0) * IN_CH + (lane & 3) * 2;
    const float* pA1 = A + (size_t)(r1 < M ? r1 : 0) * IN_CH + (lane & 3) * 2;

    const int lr  = lane & 7;
    const int seg = lane >> 3;
    const int b_kr   = (seg & 1) * 8 + lr;
    const int b_toff = (seg >> 1);

    float acc[8][4];
#pragma unroll
    for (int t = 0; t < 8; t++)
#pragma unroll
        for (int j = 0; j < 4; j++) acc[t][j] = 0.f;

    float2 f[2][4];
#pragma unroll
    for (int q = 0; q < 2; q++) {
        f[q][0] = *(const float2*)(pA0 + q * 16);
        f[q][1] = *(const float2*)(pA1 + q * 16);
        f[q][2] = *(const float2*)(pA0 + q * 16 + 8);
        f[q][3] = *(const float2*)(pA1 + q * 16 + 8);
    }

#pragma unroll
    for (int s = 0; s < 8; s++) {
        unsigned a0 = pack_h2(f[s & 1][0].x, f[s & 1][0].y);
        unsigned a1 = pack_h2(f[s & 1][1].x, f[s & 1][1].y);
        unsigned a2 = pack_h2(f[s & 1][2].x, f[s & 1][2].y);
        unsigned a3 = pack_h2(f[s & 1][3].x, f[s & 1][3].y);
        if (s + 2 < 8) {
            f[s & 1][0] = *(const float2*)(pA0 + (s + 2) * 16);
            f[s & 1][1] = *(const float2*)(pA1 + (s + 2) * 16);
            f[s & 1][2] = *(const float2*)(pA0 + (s + 2) * 16 + 8);
            f[s & 1][3] = *(const float2*)(pA1 + (s + 2) * 16 + 8);
        }

        unsigned b[8][2];
#pragma unroll
        for (int tp = 0; tp < 4; tp++) {
            unsigned bd = (unsigned)__cvta_generic_to_shared(
                sW + (s * 16 + b_kr) * SW_PITCH + (2 * tp + b_toff) * 8);
            unsigned q0, q1, q2, q3;
            asm volatile("ldmatrix.sync.aligned.m8n8.x4.trans.shared.b16 {%0,%1,%2,%3}, [%4];"
                         : "=r"(q0), "=r"(q1), "=r"(q2), "=r"(q3) : "r"(bd));
            b[2 * tp][0] = q0; b[2 * tp][1] = q1;
            b[2 * tp + 1][0] = q2; b[2 * tp + 1][1] = q3;
        }
#pragma unroll
        for (int t = 0; t < 8; t++) {
            asm volatile(
                "mma.sync.aligned.m16n8k16.row.col.f32.f16.f16.f32 "
                "{%0,%1,%2,%3}, {%4,%5,%6,%7}, {%8,%9}, {%0,%1,%2,%3};"
                : "+f"(acc[t][0]), "+f"(acc[t][1]), "+f"(acc[t][2]), "+f"(acc[t][3])
                : "r"(a0), "r"(a1), "r"(a2), "r"(a3), "r"(b[t][0]), "r"(b[t][1]));
        }
    }

    const float dv0 = (r0 < M) ? g_dinv[r0] : 0.f;
    const float dv1 = (r1 < M) ? g_dinv[r1] : 0.f;
    const int cb = (lane & 3) * 2;
#pragma unroll
    for (int t = 0; t < 8; t++) {
        int col = t * 8 + cb;
        if (r0 < M)
            *(unsigned*)(C + (size_t)r0 * HIDDEN + col) = pack_h2(dv0 * acc[t][0], dv0 * acc[t][1]);
        if (r1 < M)
            *(unsigned*)(C + (size_t)r1 * HIDDEN + col) = pack_h2(dv1 * acc[t][2], dv1 * acc[t][3]);
    }
}

// ---------------- GEMM2 (tensor core): fp16 C[M,40]=dinv*(relu(A)@W[64,40]) -
#define SW2_PITCH 40

__global__ __launch_bounds__(256) void gemm2_kernel(const __half* __restrict__ A,
                                                    const float* __restrict__ W,
                                                    __half* __restrict__ C, int M) {
    __shared__ __half sW[64 * SW2_PITCH];
    const int tid = threadIdx.x;

    for (int i = tid; i < 64 * 10; i += 256) {
        int r = i / 10, c4 = (i - r * 10) * 4;
        float4 a = *(const float4*)(W + r * NCLS + c4);
        *(uint2*)(sW + r * SW2_PITCH + c4) = make_uint2(pack_h2(a.x, a.y), pack_h2(a.z, a.w));
    }
    __syncthreads();

    const int warp = tid >> 5, lane = tid & 31;
    const int r0 = blockIdx.x * 128 + warp * 16 + (lane >> 2);
    const int r1 = r0 + 8;
    const __half* pA0 = A + (size_t)(r0 < M ? r0 : 0) * HIDDEN + (lane & 3) * 2;
    const __half* pA1 = A + (size_t)(r1 < M ? r1 : 0) * HIDDEN + (lane & 3) * 2;

    const int lr  = lane & 7;
    const int seg = lane >> 3;
    const int b_kr   = (seg & 1) * 8 + lr;
    const int b_toff = (seg >> 1);
    const int l15 = lane & 15;

    float acc[5][4];
#pragma unroll
    for (int t = 0; t < 5; t++)
#pragma unroll
        for (int j = 0; j < 4; j++) acc[t][j] = 0.f;

#pragma unroll
    for (int s = 0; s < 4; s++) {
        unsigned a0 = relu_h2(*(const unsigned*)(pA0 + s * 16));
        unsigned a1 = relu_h2(*(const unsigned*)(pA1 + s * 16));
        unsigned a2 = relu_h2(*(const unsigned*)(pA0 + s * 16 + 8));
        unsigned a3 = relu_h2(*(const unsigned*)(pA1 + s * 16 + 8));

        unsigned b[5][2];
#pragma unroll
        for (int tp = 0; tp < 2; tp++) {
            unsigned bd = (unsigned)__cvta_generic_to_shared(
                sW + (s * 16 + b_kr) * SW2_PITCH + (2 * tp + b_toff) * 8);
            unsigned q0, q1, q2, q3;
            asm volatile("ldmatrix.sync.aligned.m8n8.x4.trans.shared.b16 {%0,%1,%2,%3}, [%4];"
                         : "=r"(q0), "=r"(q1), "=r"(q2), "=r"(q3) : "r"(bd));
            b[2 * tp][0] = q0; b[2 * tp][1] = q1;
            b[2 * tp + 1][0] = q2; b[2 * tp + 1][1] = q3;
        }
        {
            unsigned bd = (unsigned)__cvta_generic_to_shared(
                sW + (s * 16 + (l15 >> 3) * 8 + (l15 & 7)) * SW2_PITCH + 32);
            unsigned q0, q1;
            asm volatile("ldmatrix.sync.aligned.m8n8.x2.trans.shared.b16 {%0,%1}, [%2];"
                         : "=r"(q0), "=r"(q1) : "r"(bd));
            b[4][0] = q0; b[4][1] = q1;
        }
#pragma unroll
        for (int t = 0; t < 5; t++) {
            asm volatile(
                "mma.sync.aligned.m16n8k16.row.col.f32.f16.f16.f32 "
                "{%0,%1,%2,%3}, {%4,%5,%6,%7}, {%8,%9}, {%0,%1,%2,%3};"
                : "+f"(acc[t][0]), "+f"(acc[t][1]), "+f"(acc[t][2]), "+f"(acc[t][3])
                : "r"(a0), "r"(a1), "r"(a2), "r"(a3), "r"(b[t][0]), "r"(b[t][1]));
        }
    }

    const float dv0 = (r0 < M) ? g_dinv[r0] : 0.f;
    const float dv1 = (r1 < M) ? g_dinv[r1] : 0.f;
    const int cb = (lane & 3) * 2;
#pragma unroll
    for (int t = 0; t < 5; t++) {
        int col = t * 8 + cb;
        if (r0 < M)
            *(unsigned*)(C + (size_t)r0 * NCLS + col) = pack_h2(dv0 * acc[t][0], dv0 * acc[t][1]);
        if (r1 < M)
            *(unsigned*)(C + (size_t)r1 * NCLS + col) = pack_h2(dv1 * acc[t][2], dv1 * acc[t][3]);
    }
}

// ---------------- CSR aggregation (unweighted sum of dinv-scaled rows) ------
// out[d] = bias + dinv_d * (feat[d] + sum_j feat[src_j]);  feat already dinv-scaled.
template<int CH, bool ZERO_DEG, typename OutT>
__global__ void aggregate_kernel(const __half* __restrict__ feat,
                                 const float* __restrict__ bias,
                                 OutT* __restrict__ out) {
    constexpr int V4 = CH / 8;       // 8 (CH=64) or 5 (CH=40)
    constexpr int EP = 32 / V4;      // 4 or 6
    int node = (blockIdx.x * blockDim.x + threadIdx.x) >> 5;
    if (node >= N_NODES) return;
    int lane = threadIdx.x & 31;
    int eg = lane / V4;
    int c  = lane - eg * V4;
    bool act = eg < EP;

    if (ZERO_DEG && lane == 0) g_deg[node] = 0;

    const int beg = g_off[node];
    const int end = g_off[node + 1];

    float acc[8];
#pragma unroll
    for (int j = 0; j < 8; j++) acc[j] = 0.f;

    if (eg == 0) {                   // self-loop row (already dinv_d-scaled)
        uint4 f = ((const uint4*)(feat + (size_t)node * CH))[c];
        h8_to_f8(f, acc);
    }

    int p = (act && beg + eg < end) ? g_adj[beg + eg] : -1;
    for (int k = beg; k < end; k += EP) {
        int kn = k + EP;
        int pn = (act && kn + eg < end) ? g_adj[kn + eg] : -1;
        if (p >= 0) {
            uint4 v = ((const uint4*)(feat + (size_t)p * CH))[c];
            float ff[8]; h8_to_f8(v, ff);
#pragma unroll
            for (int j = 0; j < 8; j++) acc[j] += ff[j];
        }
        p = pn;
    }

    const unsigned m = 0xffffffffu;
    if (EP == 4) {
#pragma unroll
        for (int j = 0; j < 8; j++) acc[j] += __shfl_down_sync(m, acc[j], 2 * V4);
#pragma unroll
        for (int j = 0; j < 8; j++) acc[j] += __shfl_down_sync(m, acc[j], V4);
    } else {  // EP == 6
#pragma unroll
        for (int j = 0; j < 8; j++) acc[j] += __shfl_down_sync(m, acc[j], 3 * V4);
#pragma unroll
        for (int j = 0; j < 8; j++) {
            float t = __shfl_down_sync(m, acc[j], 2 * V4);
            if (eg == 0) acc[j] += t;
        }
#pragma unroll
        for (int j = 0; j < 8; j++) {
            float t = __shfl_down_sync(m, acc[j], V4);
            if (eg == 0) acc[j] += t;
        }
    }

    if (eg == 0) {
        float dv = g_dinv[node];
        float4 b0 = ((const float4*)bias)[2 * c];
        float4 b1 = ((const float4*)bias)[2 * c + 1];
        float o0 = fmaf(dv, acc[0], b0.x), o1 = fmaf(dv, acc[1], b0.y);
        float o2 = fmaf(dv, acc[2], b0.z), o3 = fmaf(dv, acc[3], b0.w);
        float o4 = fmaf(dv, acc[4], b1.x), o5 = fmaf(dv, acc[5], b1.y);
        float o6 = fmaf(dv, acc[6], b1.z), o7 = fmaf(dv, acc[7], b1.w);
        if (sizeof(OutT) == 2) {
            uint4 u;
            u.x = pack_h2(o0, o1); u.y = pack_h2(o2, o3);
            u.z = pack_h2(o4, o5); u.w = pack_h2(o6, o7);
            ((uint4*)((__half*)out + (size_t)node * CH))[c] = u;
        } else {
            float4* po = (float4*)((float*)out + (size_t)node * CH);
            po[2 * c]     = make_float4(o0, o1, o2, o3);
            po[2 * c + 1] = make_float4(o4, o5, o6, o7);
        }
    }
}

// ---------------- launch ----------------------------------------------------
extern "C" void kernel_launch(void* const* d_in, const int* in_sizes, int n_in,
                              void* d_out, int out_size) {
    const float* x  = (const float*)d_in[0];
    const int*   ei = (const int*)d_in[1];
    const float* W1 = (const float*)d_in[2];
    const float* b1 = (const float*)d_in[3];
    const float* W2 = (const float*)d_in[4];
    const float* b2 = (const float*)d_in[5];
    float*       out = (float*)d_out;

    void *hw_p, *agg1_p, *h2w_p;
    cudaGetSymbolAddress(&hw_p,   g_hw);
    cudaGetSymbolAddress(&agg1_p, g_agg1);
    cudaGetSymbolAddress(&h2w_p,  g_h2w);

    constexpr int TPB = 256;

    // 1) degree histogram + packed (dst,rank) capture
    deg_kernel<<<NB_EDGE4, 256>>>(ei);
    // 2) single-kernel scan -> off/dinv
    scan_kernel<<<SCAN_NB, SCAN_TPB>>>();
    // 3) gemm1 with dinv-scaling epilogue
    gemm1_kernel<<<(N_NODES + 127) / 128, 256>>>(x, W1, (__half*)hw_p, N_NODES);
    // 4) counting sort via off + packed rank (atomic-free, no dst re-read)
    fill_kernel<<<NB_EDGE4, 256>>>(ei);

    // 5) layer1 aggregation -> fp16 (bias + dinv_d * sum)
    const int nb_warps = (N_NODES * 32 + TPB - 1) / TPB;
    aggregate_kernel<HIDDEN, false, __half>
        <<<nb_warps, TPB>>>((const __half*)hw_p, b1, (__half*)agg1_p);

    // 6) gemm2 (tensor core, relu fused, dinv-scaling epilogue)
    gemm2_kernel<<<(N_NODES + 127) / 128, 256>>>((const __half*)agg1_p, W2,
                                                 (__half*)h2w_p, N_NODES);

    // 7) layer2 aggregation -> fp32 output (re-zeroes g_deg for next call)
    aggregate_kernel<NCLS, true, float>
        <<<nb_warps, TPB>>>((const __half*)h2w_p, b2, out);
}

// round 17
// speedup vs baseline: 1.0326x; 1.0326x over previous
#include <cuda_runtime.h>
#include <cuda_fp16.h>
#include <cstdint>

#define N_NODES 100000
#define N_EDGES 1600000
#define IN_CH   128
#define HIDDEN  64
#define NCLS    40

// ---------------- scratch (device globals; no allocation allowed) ----------
__device__ int   g_is64;
__device__ int   g_deg[N_NODES];       // zero at load; re-zeroed by agg2 tail
__device__ int   g_off[N_NODES + 1];
__device__ float g_dinv[N_NODES];
__device__ int   g_bsum[128];          // lookback partials (sentinel +1); reset by deg
__device__ int   g_rank[N_EDGES];      // edge's rank within its dst (from deg atomic)
__device__ int   g_adj[N_EDGES];       // plain src index, dst-grouped
__device__ __align__(16) __half g_hw  [(size_t)N_NODES * HIDDEN];  // dinv*(X@W1) fp16
__device__ __align__(16) __half g_agg1[(size_t)N_NODES * HIDDEN];  // layer1 agg (fp16)
__device__ __align__(16) __half g_h2w [(size_t)N_NODES * NCLS];    // dinv*(relu@W2) fp16

// ---------------- helpers ----------------------------------------------------
__device__ __forceinline__ void h8_to_f8(uint4 v, float* f) {
    float2 t;
    t = __half22float2(*(__half2*)&v.x); f[0] = t.x; f[1] = t.y;
    t = __half22float2(*(__half2*)&v.y); f[2] = t.x; f[3] = t.y;
    t = __half22float2(*(__half2*)&v.z); f[4] = t.x; f[5] = t.y;
    t = __half22float2(*(__half2*)&v.w); f[6] = t.x; f[7] = t.y;
}
__device__ __forceinline__ unsigned pack_h2(float a, float b) {
    __half2 h = __float22half2_rn(make_float2(a, b));
    return *(unsigned*)&h;
}
__device__ __forceinline__ unsigned relu_h2(unsigned v) {
    __half2 h = *(__half2*)&v;
    h = __hmax2(h, __half2half2(__ushort_as_half(0)));
    return *(unsigned*)&h;
}

#define NB_EDGE4 1563
#define EDGE4_T  (NB_EDGE4 * 256)
#define SCAN_NB  128
#define SCAN_TPB 256
#define SCAN_PER 4        // 128*256*4 = 131072 >= N_NODES

// ---------------- deg: dtype detect + degree histogram + rank capture -------
__global__ void deg_kernel(const int* __restrict__ w) {
    int v = w[2 * threadIdx.x + 1] | w[2 * ((int)threadIdx.x + 256) + 1];
    int is64 = !__syncthreads_or(v);
    if (blockIdx.x == 0) {
        if (threadIdx.x == 0) g_is64 = is64;
        if (threadIdx.x < SCAN_NB) g_bsum[threadIdx.x] = 0;
    }

    int idx = blockIdx.x * 256 + threadIdx.x;
#pragma unroll
    for (int j = 0; j < 4; j++) {
        int e = idx + j * EDGE4_T;
        if (e < N_EDGES) {
            int d = is64 ? w[2 * (N_EDGES + e)] : w[N_EDGES + e];
            if ((unsigned)d >= N_NODES) d = 0;
            g_rank[e] = atomicAdd(&g_deg[d], 1);   // recycle rank for fill
        }
    }
}

// ---------------- single-kernel exclusive scan (decoupled lookback) ---------
__global__ void scan_kernel() {
    __shared__ int p[SCAN_TPB];
    __shared__ int red[SCAN_TPB];
    const int t = threadIdx.x;
    const int bid = blockIdx.x;

    int base = (bid * SCAN_TPB + t) * SCAN_PER;
    int loc[SCAN_PER];
    int s = 0;
#pragma unroll
    for (int j = 0; j < SCAN_PER; j++) {
        int i = base + j;
        int d = (i < N_NODES) ? g_deg[i] : 0;
        loc[j] = s;
        s += d;
    }
    p[t] = s;
    __syncthreads();
    for (int o = 1; o < SCAN_TPB; o <<= 1) {
        int v = (t >= o) ? p[t - o] : 0;
        __syncthreads();
        p[t] += v;
        __syncthreads();
    }
    int total = p[SCAN_TPB - 1];

    if (t == 0) {
        __threadfence();
        atomicExch(&g_bsum[bid], total + 1);   // publish with sentinel
    }

    int v = 0;
    if (t < bid) {
        while ((v = atomicAdd(&g_bsum[t], 0)) == 0) { }
        v -= 1;
    }
    red[t] = v;
    __syncthreads();
    for (int o = SCAN_TPB / 2; o > 0; o >>= 1) {
        if (t < o) red[t] += red[t + o];
        __syncthreads();
    }
    int bpre = red[0];
    if (bid == SCAN_NB - 1 && t == 0) g_off[N_NODES] = bpre + total;

    int pre = bpre + ((t > 0) ? p[t - 1] : 0);
#pragma unroll
    for (int j = 0; j < SCAN_PER; j++) {
        int i = base + j;
        if (i < N_NODES) {
            g_off[i] = pre + loc[j];
            g_dinv[i] = rsqrtf((float)(g_deg[i] + 1));  // +1 self loop
        }
    }
}

// counting-sort edges by dst; position = off[d] + rank (no atomics)
__global__ void fill_kernel(const int* __restrict__ w) {
    int idx = blockIdx.x * 256 + threadIdx.x;
    int is64 = g_is64;
#pragma unroll
    for (int j = 0; j < 4; j++) {
        int e = idx + j * EDGE4_T;
        if (e < N_EDGES) {
            int s, d;
            if (is64) { s = w[2 * e]; d = w[2 * (N_EDGES + e)]; }
            else      { s = w[e];     d = w[N_EDGES + e]; }
            if ((unsigned)s >= N_NODES) s = 0;
            if ((unsigned)d >= N_NODES) d = 0;
            g_adj[g_off[d] + g_rank[e]] = s;
        }
    }
}

// ---------------- GEMM1 (tensor core, A direct from gmem, pipelined) --------
// fp16 C[M,64] = dinv[m] * (A[M,128](fp32) @ W[128,64]); 8 warps x 16 rows.
#define SW_PITCH 72

__global__ __launch_bounds__(256) void gemm1_kernel(const float* __restrict__ A,
                                                    const float* __restrict__ W,
                                                    __half* __restrict__ C, int M) {
    __shared__ __half sW[128 * SW_PITCH];
    const int tid = threadIdx.x;

    for (int i = tid; i < 128 * 16; i += 256) {
        int r  = i >> 4;
        int c4 = (i & 15) * 4;
        float4 a = *(const float4*)(W + r * HIDDEN + c4);
        *(uint2*)(sW + r * SW_PITCH + c4) = make_uint2(pack_h2(a.x, a.y), pack_h2(a.z, a.w));
    }
    __syncthreads();

    const int warp = tid >> 5, lane = tid & 31;
    const int r0 = blockIdx.x * 128 + warp * 16 + (lane >> 2);
    const int r1 = r0 + 8;
    const float* pA0 = A + (size_t)(r0 < M ? r0 : 0) * IN_CH + (lane & 3) * 2;
    const float* pA1 = A + (size_t)(r1 < M ? r1 : 0) * IN_CH + (lane & 3) * 2;

    const int lr  = lane & 7;
    const int seg = lane >> 3;
    const int b_kr   = (seg & 1) * 8 + lr;
    const int b_toff = (seg >> 1);

    float acc[8][4];
#pragma unroll
    for (int t = 0; t < 8; t++)
#pragma unroll
        for (int j = 0; j < 4; j++) acc[t][j] = 0.f;

    float2 f[2][4];
#pragma unroll
    for (int q = 0; q < 2; q++) {
        f[q][0] = *(const float2*)(pA0 + q * 16);
        f[q][1] = *(const float2*)(pA1 + q * 16);
        f[q][2] = *(const float2*)(pA0 + q * 16 + 8);
        f[q][3] = *(const float2*)(pA1 + q * 16 + 8);
    }

#pragma unroll
    for (int s = 0; s < 8; s++) {
        unsigned a0 = pack_h2(f[s & 1][0].x, f[s & 1][0].y);
        unsigned a1 = pack_h2(f[s & 1][1].x, f[s & 1][1].y);
        unsigned a2 = pack_h2(f[s & 1][2].x, f[s & 1][2].y);
        unsigned a3 = pack_h2(f[s & 1][3].x, f[s & 1][3].y);
        if (s + 2 < 8) {
            f[s & 1][0] = *(const float2*)(pA0 + (s + 2) * 16);
            f[s & 1][1] = *(const float2*)(pA1 + (s + 2) * 16);
            f[s & 1][2] = *(const float2*)(pA0 + (s + 2) * 16 + 8);
            f[s & 1][3] = *(const float2*)(pA1 + (s + 2) * 16 + 8);
        }

        unsigned b[8][2];
#pragma unroll
        for (int tp = 0; tp < 4; tp++) {
            unsigned bd = (unsigned)__cvta_generic_to_shared(
                sW + (s * 16 + b_kr) * SW_PITCH + (2 * tp + b_toff) * 8);
            unsigned q0, q1, q2, q3;
            asm volatile("ldmatrix.sync.aligned.m8n8.x4.trans.shared.b16 {%0,%1,%2,%3}, [%4];"
                         : "=r"(q0), "=r"(q1), "=r"(q2), "=r"(q3) : "r"(bd));
            b[2 * tp][0] = q0; b[2 * tp][1] = q1;
            b[2 * tp + 1][0] = q2; b[2 * tp + 1][1] = q3;
        }
#pragma unroll
        for (int t = 0; t < 8; t++) {
            asm volatile(
                "mma.sync.aligned.m16n8k16.row.col.f32.f16.f16.f32 "
                "{%0,%1,%2,%3}, {%4,%5,%6,%7}, {%8,%9}, {%0,%1,%2,%3};"
                : "+f"(acc[t][0]), "+f"(acc[t][1]), "+f"(acc[t][2]), "+f"(acc[t][3])
                : "r"(a0), "r"(a1), "r"(a2), "r"(a3), "r"(b[t][0]), "r"(b[t][1]));
        }
    }

    const float dv0 = (r0 < M) ? g_dinv[r0] : 0.f;
    const float dv1 = (r1 < M) ? g_dinv[r1] : 0.f;
    const int cb = (lane & 3) * 2;
#pragma unroll
    for (int t = 0; t < 8; t++) {
        int col = t * 8 + cb;
        if (r0 < M)
            *(unsigned*)(C + (size_t)r0 * HIDDEN + col) = pack_h2(dv0 * acc[t][0], dv0 * acc[t][1]);
        if (r1 < M)
            *(unsigned*)(C + (size_t)r1 * HIDDEN + col) = pack_h2(dv1 * acc[t][2], dv1 * acc[t][3]);
    }
}

// ---------------- GEMM2 (tensor core): fp16 C[M,40]=dinv*(relu(A)@W[64,40]) -
#define SW2_PITCH 40

__global__ __launch_bounds__(256) void gemm2_kernel(const __half* __restrict__ A,
                                                    const float* __restrict__ W,
                                                    __half* __restrict__ C, int M) {
    __shared__ __half sW[64 * SW2_PITCH];
    const int tid = threadIdx.x;

    for (int i = tid; i < 64 * 10; i += 256) {
        int r = i / 10, c4 = (i - r * 10) * 4;
        float4 a = *(const float4*)(W + r * NCLS + c4);
        *(uint2*)(sW + r * SW2_PITCH + c4) = make_uint2(pack_h2(a.x, a.y), pack_h2(a.z, a.w));
    }
    __syncthreads();

    const int warp = tid >> 5, lane = tid & 31;
    const int r0 = blockIdx.x * 128 + warp * 16 + (lane >> 2);
    const int r1 = r0 + 8;
    const __half* pA0 = A + (size_t)(r0 < M ? r0 : 0) * HIDDEN + (lane & 3) * 2;
    const __half* pA1 = A + (size_t)(r1 < M ? r1 : 0) * HIDDEN + (lane & 3) * 2;

    const int lr  = lane & 7;
    const int seg = lane >> 3;
    const int b_kr   = (seg & 1) * 8 + lr;
    const int b_toff = (seg >> 1);
    const int l15 = lane & 15;

    float acc[5][4];
#pragma unroll
    for (int t = 0; t < 5; t++)
#pragma unroll
        for (int j = 0; j < 4; j++) acc[t][j] = 0.f;

#pragma unroll
    for (int s = 0; s < 4; s++) {
        unsigned a0 = relu_h2(*(const unsigned*)(pA0 + s * 16));
        unsigned a1 = relu_h2(*(const unsigned*)(pA1 + s * 16));
        unsigned a2 = relu_h2(*(const unsigned*)(pA0 + s * 16 + 8));
        unsigned a3 = relu_h2(*(const unsigned*)(pA1 + s * 16 + 8));

        unsigned b[5][2];
#pragma unroll
        for (int tp = 0; tp < 2; tp++) {
            unsigned bd = (unsigned)__cvta_generic_to_shared(
                sW + (s * 16 + b_kr) * SW2_PITCH + (2 * tp + b_toff) * 8);
            unsigned q0, q1, q2, q3;
            asm volatile("ldmatrix.sync.aligned.m8n8.x4.trans.shared.b16 {%0,%1,%2,%3}, [%4];"
                         : "=r"(q0), "=r"(q1), "=r"(q2), "=r"(q3) : "r"(bd));
            b[2 * tp][0] = q0; b[2 * tp][1] = q1;
            b[2 * tp + 1][0] = q2; b[2 * tp + 1][1] = q3;
        }
        {
            unsigned bd = (unsigned)__cvta_generic_to_shared(
                sW + (s * 16 + (l15 >> 3) * 8 + (l15 & 7)) * SW2_PITCH + 32);
            unsigned q0, q1;
            asm volatile("ldmatrix.sync.aligned.m8n8.x2.trans.shared.b16 {%0,%1}, [%2];"
                         : "=r"(q0), "=r"(q1) : "r"(bd));
            b[4][0] = q0; b[4][1] = q1;
        }
#pragma unroll
        for (int t = 0; t < 5; t++) {
            asm volatile(
                "mma.sync.aligned.m16n8k16.row.col.f32.f16.f16.f32 "
                "{%0,%1,%2,%3}, {%4,%5,%6,%7}, {%8,%9}, {%0,%1,%2,%3};"
                : "+f"(acc[t][0]), "+f"(acc[t][1]), "+f"(acc[t][2]), "+f"(acc[t][3])
                : "r"(a0), "r"(a1), "r"(a2), "r"(a3), "r"(b[t][0]), "r"(b[t][1]));
        }
    }

    const float dv0 = (r0 < M) ? g_dinv[r0] : 0.f;
    const float dv1 = (r1 < M) ? g_dinv[r1] : 0.f;
    const int cb = (lane & 3) * 2;
#pragma unroll
    for (int t = 0; t < 5; t++) {
        int col = t * 8 + cb;
        if (r0 < M)
            *(unsigned*)(C + (size_t)r0 * NCLS + col) = pack_h2(dv0 * acc[t][0], dv0 * acc[t][1]);
        if (r1 < M)
            *(unsigned*)(C + (size_t)r1 * NCLS + col) = pack_h2(dv1 * acc[t][2], dv1 * acc[t][3]);
    }
}

// ---------------- CSR aggregation (unweighted sum of dinv-scaled rows) ------
// out[d] = bias + dinv_d * (feat[d] + sum_j feat[src_j]);  feat already dinv-scaled.
template<int CH, bool ZERO_DEG, typename OutT>
__global__ void aggregate_kernel(const __half* __restrict__ feat,
                                 const float* __restrict__ bias,
                                 OutT* __restrict__ out) {
    constexpr int V4 = CH / 8;       // 8 (CH=64) or 5 (CH=40)
    constexpr int EP = 32 / V4;      // 4 or 6
    int node = (blockIdx.x * blockDim.x + threadIdx.x) >> 5;
    if (node >= N_NODES) return;
    int lane = threadIdx.x & 31;
    int eg = lane / V4;
    int c  = lane - eg * V4;
    bool act = eg < EP;

    if (ZERO_DEG && lane == 0) g_deg[node] = 0;

    const int beg = g_off[node];
    const int end = g_off[node + 1];

    float acc[8];
#pragma unroll
    for (int j = 0; j < 8; j++) acc[j] = 0.f;

    if (eg == 0) {                   // self-loop row (already dinv_d-scaled)
        uint4 f = ((const uint4*)(feat + (size_t)node * CH))[c];
        h8_to_f8(f, acc);
    }

    int p = (act && beg + eg < end) ? g_adj[beg + eg] : -1;
    for (int k = beg; k < end; k += EP) {
        int kn = k + EP;
        int pn = (act && kn + eg < end) ? g_adj[kn + eg] : -1;
        if (p >= 0) {
            uint4 v = ((const uint4*)(feat + (size_t)p * CH))[c];
            float ff[8]; h8_to_f8(v, ff);
#pragma unroll
            for (int j = 0; j < 8; j++) acc[j] += ff[j];
        }
        p = pn;
    }

    const unsigned m = 0xffffffffu;
    if (EP == 4) {
#pragma unroll
        for (int j = 0; j < 8; j++) acc[j] += __shfl_down_sync(m, acc[j], 2 * V4);
#pragma unroll
        for (int j = 0; j < 8; j++) acc[j] += __shfl_down_sync(m, acc[j], V4);
    } else {  // EP == 6
#pragma unroll
        for (int j = 0; j < 8; j++) acc[j] += __shfl_down_sync(m, acc[j], 3 * V4);
#pragma unroll
        for (int j = 0; j < 8; j++) {
            float t = __shfl_down_sync(m, acc[j], 2 * V4);
            if (eg == 0) acc[j] += t;
        }
#pragma unroll
        for (int j = 0; j < 8; j++) {
            float t = __shfl_down_sync(m, acc[j], V4);
            if (eg == 0) acc[j] += t;
        }
    }

    if (eg == 0) {
        float dv = g_dinv[node];
        float4 b0 = ((const float4*)bias)[2 * c];
        float4 b1 = ((const float4*)bias)[2 * c + 1];
        float o0 = fmaf(dv, acc[0], b0.x), o1 = fmaf(dv, acc[1], b0.y);
        float o2 = fmaf(dv, acc[2], b0.z), o3 = fmaf(dv, acc[3], b0.w);
        float o4 = fmaf(dv, acc[4], b1.x), o5 = fmaf(dv, acc[5], b1.y);
        float o6 = fmaf(dv, acc[6], b1.z), o7 = fmaf(dv, acc[7], b1.w);
        if (sizeof(OutT) == 2) {
            uint4 u;
            u.x = pack_h2(o0, o1); u.y = pack_h2(o2, o3);
            u.z = pack_h2(o4, o5); u.w = pack_h2(o6, o7);
            ((uint4*)((__half*)out + (size_t)node * CH))[c] = u;
        } else {
            float4* po = (float4*)((float*)out + (size_t)node * CH);
            po[2 * c]     = make_float4(o0, o1, o2, o3);
            po[2 * c + 1] = make_float4(o4, o5, o6, o7);
        }
    }
}

// ---------------- launch ----------------------------------------------------
extern "C" void kernel_launch(void* const* d_in, const int* in_sizes, int n_in,
                              void* d_out, int out_size) {
    const float* x  = (const float*)d_in[0];
    const int*   ei = (const int*)d_in[1];
    const float* W1 = (const float*)d_in[2];
    const float* b1 = (const float*)d_in[3];
    const float* W2 = (const float*)d_in[4];
    const float* b2 = (const float*)d_in[5];
    float*       out = (float*)d_out;

    void *hw_p, *agg1_p, *h2w_p;
    cudaGetSymbolAddress(&hw_p,   g_hw);
    cudaGetSymbolAddress(&agg1_p, g_agg1);
    cudaGetSymbolAddress(&h2w_p,  g_h2w);

    constexpr int TPB = 256;

    // fork-join handles (created per call; intentionally not destroyed —
    // destroying a forked stream mid-capture invalidates the capture, and
    // kernel_launch runs on the host only a handful of times).
    cudaStream_t s2;
    cudaEvent_t evF, evJ;
    cudaStreamCreateWithFlags(&s2, cudaStreamNonBlocking);
    cudaEventCreateWithFlags(&evF, cudaEventDisableTiming);
    cudaEventCreateWithFlags(&evJ, cudaEventDisableTiming);

    // 1) degree histogram + per-edge rank capture
    deg_kernel<<<NB_EDGE4, 256>>>(ei);
    // 2) single-kernel scan -> off/dinv
    scan_kernel<<<SCAN_NB, SCAN_TPB>>>();

    // fork: gemm1 (DRAM-bound, needs dinv) runs on s2 concurrently with
    // fill (L2-random-bound, needs off/rank) on the main stream.
    cudaEventRecord(evF, 0);
    cudaStreamWaitEvent(s2, evF, 0);
    gemm1_kernel<<<(N_NODES + 127) / 128, 256, 0, s2>>>(x, W1, (__half*)hw_p, N_NODES);
    cudaEventRecord(evJ, s2);

    // 3) counting sort via off+rank (atomic-free), main stream
    fill_kernel<<<NB_EDGE4, 256>>>(ei);

    // join: agg1 needs both g_hw (s2) and g_adj (main)
    cudaStreamWaitEvent(0, evJ, 0);

    // 4) layer1 aggregation -> fp16 (bias + dinv_d * sum)
    const int nb_warps = (N_NODES * 32 + TPB - 1) / TPB;
    aggregate_kernel<HIDDEN, false, __half>
        <<<nb_warps, TPB>>>((const __half*)hw_p, b1, (__half*)agg1_p);

    // 5) gemm2 (tensor core, relu fused, dinv-scaling epilogue)
    gemm2_kernel<<<(N_NODES + 127) / 128, 256>>>((const __half*)agg1_p, W2,
                                                 (__half*)h2w_p, N_NODES);

    // 6) layer2 aggregation -> fp32 output (re-zeroes g_deg for next call)
    aggregate_kernel<NCLS, true, float>
        <<<nb_warps, TPB>>>((const __half*)h2w_p, b2, out);
}